// round 2
// baseline (speedup 1.0000x reference)
#include <cuda_runtime.h>
#include <cstdint>
#include <math.h>

// Problem dims (fixed by the dataset)
#define N_TOK 8192
#define DIM   1024

// Scratch: Q, K, V (32 MB each) + scores (256 MB). __device__ globals are the
// allowed allocation-free scratch mechanism.
__device__ float g_q[(size_t)N_TOK * DIM];
__device__ float g_k[(size_t)N_TOK * DIM];
__device__ float g_v[(size_t)N_TOK * DIM];
__device__ float g_s[(size_t)N_TOK * N_TOK];

using ull = unsigned long long;

// ---- packed fp32x2 helpers (sm_103a FFMA2 path; 2x fp32 throughput) ----
__device__ __forceinline__ ull pack2_dup(float x) {
    ull r;
    asm("mov.b64 %0, {%1, %1};" : "=l"(r) : "f"(x));
    return r;
}
__device__ __forceinline__ void fma2(ull& c, ull a, ull b) {
    asm("fma.rn.f32x2 %0, %1, %2, %0;" : "+l"(c) : "l"(a), "l"(b));
}
__device__ __forceinline__ float2 unpack2(ull c) {
    float2 f;
    asm("mov.b64 {%0, %1}, %2;" : "=f"(f.x), "=f"(f.y) : "l"(c));
    return f;
}

// ============================================================================
// GEMM NT:  C[m,n] = sum_k A[m,k] * B[n,k]  (+ bias[n] if bias != nullptr)
//   A: [M,K] row-major (lda=K), B: [N,K] row-major (ldb=K), C: [M,N] (ldc=N)
// Tile: 128x128x16, 256 threads, 8x8 micro-tile per thread, FFMA2 inner loop.
// Requires M%128==0, N%128==0, K%16==0 (true for all uses here).
// ============================================================================
__global__ __launch_bounds__(256, 2)
void gemm_nt(const float* __restrict__ A, const float* __restrict__ B,
             const float* __restrict__ bias, float* __restrict__ C,
             int M, int N, int K)
{
    __shared__ float As[16][128];
    __shared__ float Bs[16][128];

    const int m0 = blockIdx.y * 128;
    const int n0 = blockIdx.x * 128;
    const int t  = threadIdx.x;
    const int tx = t & 15;   // n-group
    const int ty = t >> 4;   // m-group

    ull acc[8][4];
#pragma unroll
    for (int i = 0; i < 8; i++)
#pragma unroll
        for (int j = 0; j < 4; j++) acc[i][j] = 0ULL;

    const int r0 = t >> 2;          // row 0..63 (second half +64)
    const int c4 = (t & 3) * 4;     // k offset within tile: 0,4,8,12

    for (int kt = 0; kt < K; kt += 16) {
#pragma unroll
        for (int h = 0; h < 2; h++) {
            const int r = r0 + h * 64;
            float4 va = *(const float4*)(A + (size_t)(m0 + r) * K + kt + c4);
            As[c4 + 0][r] = va.x; As[c4 + 1][r] = va.y;
            As[c4 + 2][r] = va.z; As[c4 + 3][r] = va.w;
            float4 vb = *(const float4*)(B + (size_t)(n0 + r) * K + kt + c4);
            Bs[c4 + 0][r] = vb.x; Bs[c4 + 1][r] = vb.y;
            Bs[c4 + 2][r] = vb.z; Bs[c4 + 3][r] = vb.w;
        }
        __syncthreads();

#pragma unroll
        for (int k = 0; k < 16; k++) {
            const float4 a0 = *(const float4*)&As[k][ty * 8];
            const float4 a1 = *(const float4*)&As[k][ty * 8 + 4];
            const ulonglong2 bb0 = *(const ulonglong2*)&Bs[k][tx * 8];
            const ulonglong2 bb1 = *(const ulonglong2*)&Bs[k][tx * 8 + 4];
            ull b[4] = { bb0.x, bb0.y, bb1.x, bb1.y };
            float am[8] = { a0.x, a0.y, a0.z, a0.w, a1.x, a1.y, a1.z, a1.w };
#pragma unroll
            for (int m = 0; m < 8; m++) {
                const ull ap = pack2_dup(am[m]);
                fma2(acc[m][0], ap, b[0]);
                fma2(acc[m][1], ap, b[1]);
                fma2(acc[m][2], ap, b[2]);
                fma2(acc[m][3], ap, b[3]);
            }
        }
        __syncthreads();
    }

    float bv[8];
#pragma unroll
    for (int j = 0; j < 8; j++)
        bv[j] = bias ? bias[n0 + tx * 8 + j] : 0.0f;

#pragma unroll
    for (int m = 0; m < 8; m++) {
        const int cm = m0 + ty * 8 + m;
        const int cn = n0 + tx * 8;
        float2 o0 = unpack2(acc[m][0]);
        float2 o1 = unpack2(acc[m][1]);
        float2 o2 = unpack2(acc[m][2]);
        float2 o3 = unpack2(acc[m][3]);
        float4 w0 = make_float4(o0.x + bv[0], o0.y + bv[1], o1.x + bv[2], o1.y + bv[3]);
        float4 w1 = make_float4(o2.x + bv[4], o2.y + bv[5], o3.x + bv[6], o3.y + bv[7]);
        *(float4*)(C + (size_t)cm * N + cn)     = w0;
        *(float4*)(C + (size_t)cm * N + cn + 4) = w1;
    }
}

// ============================================================================
// GEMM NN:  C[m,n] = sum_k A[m,k] * B[k,n]
//   A: [M,K] row-major (lda=K), B: [K,N] row-major (ldb=N), C: [M,N]
// Same tiling as above; only the B tile load differs (no transpose needed).
// ============================================================================
__global__ __launch_bounds__(256, 2)
void gemm_nn(const float* __restrict__ A, const float* __restrict__ B,
             float* __restrict__ C, int M, int N, int K)
{
    __shared__ float As[16][128];
    __shared__ float Bs[16][128];

    const int m0 = blockIdx.y * 128;
    const int n0 = blockIdx.x * 128;
    const int t  = threadIdx.x;
    const int tx = t & 15;
    const int ty = t >> 4;

    ull acc[8][4];
#pragma unroll
    for (int i = 0; i < 8; i++)
#pragma unroll
        for (int j = 0; j < 4; j++) acc[i][j] = 0ULL;

    const int ra = t >> 2;          // A-load row 0..63
    const int ca = (t & 3) * 4;     // A-load k offset
    const int rb = t >> 5;          // B-load k-row 0..7 (second half +8)
    const int cb = (t & 31) * 4;    // B-load n offset

    for (int kt = 0; kt < K; kt += 16) {
#pragma unroll
        for (int h = 0; h < 2; h++) {
            const int r = ra + h * 64;
            float4 va = *(const float4*)(A + (size_t)(m0 + r) * K + kt + ca);
            As[ca + 0][r] = va.x; As[ca + 1][r] = va.y;
            As[ca + 2][r] = va.z; As[ca + 3][r] = va.w;
            const int kr = rb + h * 8;
            float4 vb = *(const float4*)(B + (size_t)(kt + kr) * N + n0 + cb);
            *(float4*)&Bs[kr][cb] = vb;
        }
        __syncthreads();

#pragma unroll
        for (int k = 0; k < 16; k++) {
            const float4 a0 = *(const float4*)&As[k][ty * 8];
            const float4 a1 = *(const float4*)&As[k][ty * 8 + 4];
            const ulonglong2 bb0 = *(const ulonglong2*)&Bs[k][tx * 8];
            const ulonglong2 bb1 = *(const ulonglong2*)&Bs[k][tx * 8 + 4];
            ull b[4] = { bb0.x, bb0.y, bb1.x, bb1.y };
            float am[8] = { a0.x, a0.y, a0.z, a0.w, a1.x, a1.y, a1.z, a1.w };
#pragma unroll
            for (int m = 0; m < 8; m++) {
                const ull ap = pack2_dup(am[m]);
                fma2(acc[m][0], ap, b[0]);
                fma2(acc[m][1], ap, b[1]);
                fma2(acc[m][2], ap, b[2]);
                fma2(acc[m][3], ap, b[3]);
            }
        }
        __syncthreads();
    }

#pragma unroll
    for (int m = 0; m < 8; m++) {
        const int cm = m0 + ty * 8 + m;
        const int cn = n0 + tx * 8;
        float2 o0 = unpack2(acc[m][0]);
        float2 o1 = unpack2(acc[m][1]);
        float2 o2 = unpack2(acc[m][2]);
        float2 o3 = unpack2(acc[m][3]);
        *(float4*)(C + (size_t)cm * N + cn)     = make_float4(o0.x, o0.y, o1.x, o1.y);
        *(float4*)(C + (size_t)cm * N + cn + 4) = make_float4(o2.x, o2.y, o3.x, o3.y);
    }
}

// ============================================================================
// Row softmax, in place. One block per row (8192 cols), 256 threads,
// 32 elements per thread held in registers.
// ============================================================================
__global__ __launch_bounds__(256)
void softmax_rows(float* __restrict__ S)
{
    const int row = blockIdx.x;
    float* p = S + (size_t)row * N_TOK;
    const int t = threadIdx.x;
    const int lane = t & 31;
    const int warp = t >> 5;

    __shared__ float red[10];   // [0..7] warp partials, [8] max, [9] sum

    float4 v[8];
    float mx = -INFINITY;
#pragma unroll
    for (int i = 0; i < 8; i++) {
        v[i] = *(const float4*)(p + (size_t)(i * 256 + t) * 4);
        mx = fmaxf(mx, fmaxf(fmaxf(v[i].x, v[i].y), fmaxf(v[i].z, v[i].w)));
    }
#pragma unroll
    for (int o = 16; o > 0; o >>= 1)
        mx = fmaxf(mx, __shfl_xor_sync(0xFFFFFFFFu, mx, o));
    if (lane == 0) red[warp] = mx;
    __syncthreads();
    if (t == 0) {
        float m = red[0];
#pragma unroll
        for (int w = 1; w < 8; w++) m = fmaxf(m, red[w]);
        red[8] = m;
    }
    __syncthreads();
    mx = red[8];

    float sum = 0.0f;
#pragma unroll
    for (int i = 0; i < 8; i++) {
        v[i].x = __expf(v[i].x - mx);
        v[i].y = __expf(v[i].y - mx);
        v[i].z = __expf(v[i].z - mx);
        v[i].w = __expf(v[i].w - mx);
        sum += (v[i].x + v[i].y) + (v[i].z + v[i].w);
    }
#pragma unroll
    for (int o = 16; o > 0; o >>= 1)
        sum += __shfl_xor_sync(0xFFFFFFFFu, sum, o);
    if (lane == 0) red[warp] = sum;
    __syncthreads();
    if (t == 0) {
        float s = 0.0f;
#pragma unroll
        for (int w = 0; w < 8; w++) s += red[w];
        red[9] = s;
    }
    __syncthreads();
    const float inv = 1.0f / red[9];

#pragma unroll
    for (int i = 0; i < 8; i++) {
        v[i].x *= inv; v[i].y *= inv; v[i].z *= inv; v[i].w *= inv;
        *(float4*)(p + (size_t)(i * 256 + t) * 4) = v[i];
    }
}

// ============================================================================
// Launch: QKV (3x GEMM-NT + bias) -> S = Q K^T (GEMM-NT) -> softmax -> O = P V
// All plain kernel launches on the legacy stream: graph-capturable, alloc-free.
// ============================================================================
extern "C" void kernel_launch(void* const* d_in, const int* in_sizes, int n_in,
                              void* d_out, int out_size)
{
    const float* emb = (const float*)d_in[0];
    const float* Wq  = (const float*)d_in[1];
    const float* bq  = (const float*)d_in[2];
    const float* Wk  = (const float*)d_in[3];
    const float* bk  = (const float*)d_in[4];
    const float* Wv  = (const float*)d_in[5];
    const float* bv  = (const float*)d_in[6];
    float* out = (float*)d_out;

    float *q, *k, *v, *s;
    cudaGetSymbolAddress((void**)&q, g_q);
    cudaGetSymbolAddress((void**)&k, g_k);
    cudaGetSymbolAddress((void**)&v, g_v);
    cudaGetSymbolAddress((void**)&s, g_s);

    // QKV projections: [8192,1024] @ [1024,1024]^T + bias
    gemm_nt<<<dim3(DIM / 128, N_TOK / 128), 256>>>(emb, Wq, bq, q, N_TOK, DIM, DIM);
    gemm_nt<<<dim3(DIM / 128, N_TOK / 128), 256>>>(emb, Wk, bk, k, N_TOK, DIM, DIM);
    gemm_nt<<<dim3(DIM / 128, N_TOK / 128), 256>>>(emb, Wv, bv, v, N_TOK, DIM, DIM);

    // Scores: [8192,1024] @ [8192,1024]^T -> [8192,8192]
    gemm_nt<<<dim3(N_TOK / 128, N_TOK / 128), 256>>>(q, k, nullptr, s, N_TOK, N_TOK, DIM);

    // Row softmax in place
    softmax_rows<<<N_TOK, 256>>>(s);

    // Output: [8192,8192] @ [8192,1024] -> [8192,1024] (== [8192,1,1024])
    gemm_nn<<<dim3(DIM / 128, N_TOK / 128), 256>>>(s, v, out, N_TOK, DIM, N_TOK);
}

// round 4
// speedup vs baseline: 2.1591x; 2.1591x over previous
#include <cuda_runtime.h>
#include <cuda_fp16.h>
#include <cstdint>
#include <math.h>

#define N_TOK 8192
#define DIM   1024

// ----------------------------- scratch -------------------------------------
__device__ __align__(256) __half g_eh[(size_t)N_TOK * DIM];
__device__ __align__(256) __half g_el[(size_t)N_TOK * DIM];
__device__ __align__(256) __half g_wh[(size_t)3 * DIM * DIM];
__device__ __align__(256) __half g_wl[(size_t)3 * DIM * DIM];
__device__ __align__(256) __half g_qh[(size_t)N_TOK * DIM];
__device__ __align__(256) __half g_ql[(size_t)N_TOK * DIM];
__device__ __align__(256) __half g_kh[(size_t)N_TOK * DIM];
__device__ __align__(256) __half g_kl[(size_t)N_TOK * DIM];
__device__ __align__(256) __half g_vth[(size_t)DIM * N_TOK];  // V^T hi [D][N]
__device__ __align__(256) __half g_vtl[(size_t)DIM * N_TOK];  // V^T lo
__device__ __align__(256) float  g_s[(size_t)N_TOK * N_TOK];
__device__ __align__(256) __half g_ph[(size_t)N_TOK * N_TOK];
__device__ __align__(256) __half g_pl[(size_t)N_TOK * N_TOK];

// ----------------------------- helpers -------------------------------------
__device__ __forceinline__ uint32_t smem_u32(const void* p) {
    uint32_t a;
    asm("{ .reg .u64 t; cvta.to.shared.u64 t, %1; cvt.u32.u64 %0, t; }" : "=r"(a) : "l"(p));
    return a;
}
__device__ __forceinline__ void cp16(uint32_t dst, const void* src) {
    asm volatile("cp.async.cg.shared.global [%0], [%1], 16;" :: "r"(dst), "l"(src));
}
__device__ __forceinline__ void cp_commit() { asm volatile("cp.async.commit_group;" ::: "memory"); }
template <int N> __device__ __forceinline__ void cp_wait() {
    asm volatile("cp.async.wait_group %0;" :: "n"(N) : "memory");
}

#define LDSM4(r, addr) \
    asm volatile("ldmatrix.sync.aligned.m8n8.x4.shared.b16 {%0,%1,%2,%3}, [%4];" \
                 : "=r"((r)[0]), "=r"((r)[1]), "=r"((r)[2]), "=r"((r)[3]) : "r"(addr))

#define MMA16816(c, a, b0, b1) \
    asm volatile("mma.sync.aligned.m16n8k16.row.col.f32.f16.f16.f32 " \
                 "{%0,%1,%2,%3},{%4,%5,%6,%7},{%8,%9},{%0,%1,%2,%3};" \
                 : "+f"((c)[0]), "+f"((c)[1]), "+f"((c)[2]), "+f"((c)[3]) \
                 : "r"((a)[0]), "r"((a)[1]), "r"((a)[2]), "r"((a)[3]), "r"(b0), "r"(b1))

// ----------------------------- split GEMM ----------------------------------
// C[M,N] = (Ah+Al)[M,K] @ (Bh+Bl)[N,K]^T (+bias)
// biasMode: 0 none, 1 per-col, 2 per-row.  outMode: 0 -> f32 Cf, 1 -> Ch/Cl split.
// Tile 128x128, kc=32, 3-stage cp.async pipeline, 8 warps (2m x 4n), warp 64x32.
#define KC 32
#define ROWP 80                 // smem row pitch in bytes (32 halves + 8 pad)
#define TILEB (128 * ROWP)      // 10240 B per operand tile
#define STAGEB (4 * TILEB)      // Ah, Al, Bh, Bl
#define GSMEM (3 * STAGEB)      // 3 stages = 122880 B

__global__ __launch_bounds__(256, 1)
void gemm_sp(const __half* __restrict__ Ah, const __half* __restrict__ Al, int lda,
             const __half* __restrict__ Bh, const __half* __restrict__ Bl, int ldb,
             const float* __restrict__ bias, int biasMode,
             float* __restrict__ Cf, __half* __restrict__ Ch, __half* __restrict__ Cl,
             int ldc, int K, int outMode)
{
    extern __shared__ char smem[];
    const uint32_t sb = smem_u32(smem);
    const int t = threadIdx.x, lane = t & 31, wid = t >> 5;
    const int wm = wid >> 2, wn = wid & 3;         // 2 x 4 warp grid
    const int m0 = blockIdx.y * 128, n0 = blockIdx.x * 128;
    const int S = K / KC;

    // per-stage loader: 4 tiles x 128 rows x 64B, 2048 cp16 total, 8 per thread
    auto load_stage = [&](int s, int buf) {
        const int kt = s * KC;
        const uint32_t base = sb + (uint32_t)buf * STAGEB;
#pragma unroll
        for (int i = 0; i < 8; i++) {
            const int tile = i >> 1;               // 0:Ah 1:Al 2:Bh 3:Bl
            const int cid = (i & 1) * 256 + t;     // 0..511 within tile
            const int row = cid >> 2, ch = cid & 3;
            const uint32_t so = base + tile * TILEB + row * ROWP + ch * 16;
            const __half* gp;
            if (tile == 0)      gp = Ah + (size_t)(m0 + row) * lda + kt + ch * 8;
            else if (tile == 1) gp = Al + (size_t)(m0 + row) * lda + kt + ch * 8;
            else if (tile == 2) gp = Bh + (size_t)(n0 + row) * ldb + kt + ch * 8;
            else                gp = Bl + (size_t)(n0 + row) * ldb + kt + ch * 8;
            cp16(so, gp);
        }
        cp_commit();
    };

    float c[4][4][4];
#pragma unroll
    for (int i = 0; i < 4; i++)
#pragma unroll
        for (int j = 0; j < 4; j++)
#pragma unroll
            for (int q = 0; q < 4; q++) c[i][j][q] = 0.0f;

    load_stage(0, 0);
    if (S > 1) load_stage(1, 1);
    if (S > 2) load_stage(2, 2);

    const uint32_t arow = (uint32_t)(wm * 64 + (lane & 15));
    const uint32_t brow = (uint32_t)(wn * 32 + (lane & 15));
    const uint32_t kbyte = ((lane >> 4) << 3) * 2;   // 0 or 16

    for (int s = 0; s < S; s++) {
        if (s < S - 2) cp_wait<2>(); else if (s == S - 2) cp_wait<1>(); else cp_wait<0>();
        __syncthreads();
        const uint32_t base = sb + (uint32_t)(s % 3) * STAGEB;

#pragma unroll
        for (int kh = 0; kh < 2; kh++) {
            const uint32_t ko = kh * 32 + kbyte;   // byte offset of k0 within row
            uint32_t ah[4][4], al[4][4], bh[2][4], bl[2][4];
#pragma unroll
            for (int mi = 0; mi < 4; mi++) {
                const uint32_t ro = (arow + mi * 16) * ROWP + ko;
                LDSM4(ah[mi], base + ro);
                LDSM4(al[mi], base + TILEB + ro);
            }
#pragma unroll
            for (int g = 0; g < 2; g++) {
                const uint32_t ro = (brow + g * 16) * ROWP + ko;
                LDSM4(bh[g], base + 2 * TILEB + ro);
                LDSM4(bl[g], base + 3 * TILEB + ro);
            }
            // pass 1: Ah*Bh, pass 2: Al*Bh, pass 3: Ah*Bl
#pragma unroll
            for (int mi = 0; mi < 4; mi++)
#pragma unroll
                for (int ni = 0; ni < 4; ni++)
                    MMA16816(c[mi][ni], ah[mi], bh[ni >> 1][ni & 1], bh[ni >> 1][(ni & 1) + 2]);
#pragma unroll
            for (int mi = 0; mi < 4; mi++)
#pragma unroll
                for (int ni = 0; ni < 4; ni++)
                    MMA16816(c[mi][ni], al[mi], bh[ni >> 1][ni & 1], bh[ni >> 1][(ni & 1) + 2]);
#pragma unroll
            for (int mi = 0; mi < 4; mi++)
#pragma unroll
                for (int ni = 0; ni < 4; ni++)
                    MMA16816(c[mi][ni], ah[mi], bl[ni >> 1][ni & 1], bl[ni >> 1][(ni & 1) + 2]);
        }
        __syncthreads();
        if (s + 3 < S) load_stage(s + 3, s % 3);
    }

    // ----------------------------- epilogue --------------------------------
    const int rbase = m0 + wm * 64 + (lane >> 2);
    const int cbase = n0 + wn * 32 + (lane & 3) * 2;
#pragma unroll
    for (int mi = 0; mi < 4; mi++) {
#pragma unroll
        for (int ni = 0; ni < 4; ni++) {
            const int col = cbase + ni * 8;
            float bc0 = 0.0f, bc1 = 0.0f;
            if (biasMode == 1) { bc0 = bias[col]; bc1 = bias[col + 1]; }
#pragma unroll
            for (int h = 0; h < 2; h++) {
                const int row = rbase + mi * 16 + h * 8;
                float v0 = c[mi][ni][2 * h + 0] + bc0;
                float v1 = c[mi][ni][2 * h + 1] + bc1;
                if (biasMode == 2) { const float br = bias[row]; v0 += br; v1 += br; }
                const size_t off = (size_t)row * ldc + col;
                if (outMode == 0) {
                    *(float2*)(Cf + off) = make_float2(v0, v1);
                } else {
                    const __half h0 = __float2half(v0), h1 = __float2half(v1);
                    const __half l0 = __float2half(v0 - __half2float(h0));
                    const __half l1 = __float2half(v1 - __half2float(h1));
                    __half2 hp = __halves2half2(h0, h1), lp = __halves2half2(l0, l1);
                    *(uint32_t*)(Ch + off) = *(uint32_t*)&hp;
                    *(uint32_t*)(Cl + off) = *(uint32_t*)&lp;
                }
            }
        }
    }
}

// ----------------------------- elementwise split ---------------------------
__global__ __launch_bounds__(256)
void split_f32(const float* __restrict__ x, __half* __restrict__ h,
               __half* __restrict__ l, int n4)
{
    int i = blockIdx.x * 256 + threadIdx.x;
    if (i >= n4) return;
    float4 v = ((const float4*)x)[i];
    __half h0 = __float2half(v.x), h1 = __float2half(v.y);
    __half h2 = __float2half(v.z), h3 = __float2half(v.w);
    __half2 a = __halves2half2(h0, h1), b = __halves2half2(h2, h3);
    __half2 cc = __halves2half2(__float2half(v.x - __half2float(h0)), __float2half(v.y - __half2float(h1)));
    __half2 d = __halves2half2(__float2half(v.z - __half2float(h2)), __float2half(v.w - __half2float(h3)));
    ((uint2*)h)[i] = make_uint2(*(uint32_t*)&a, *(uint32_t*)&b);
    ((uint2*)l)[i] = make_uint2(*(uint32_t*)&cc, *(uint32_t*)&d);
}

// ----------------------------- softmax + split -----------------------------
__global__ __launch_bounds__(256)
void softmax_split(const float* __restrict__ S, __half* __restrict__ Ph,
                   __half* __restrict__ Pl)
{
    const size_t row = blockIdx.x;
    const float* p = S + row * N_TOK;
    const int t = threadIdx.x, lane = t & 31, warp = t >> 5;
    __shared__ float red[10];

    float4 v[8];
    float mx = -INFINITY;
#pragma unroll
    for (int i = 0; i < 8; i++) {
        v[i] = *(const float4*)(p + (size_t)(i * 256 + t) * 4);
        mx = fmaxf(mx, fmaxf(fmaxf(v[i].x, v[i].y), fmaxf(v[i].z, v[i].w)));
    }
#pragma unroll
    for (int o = 16; o > 0; o >>= 1) mx = fmaxf(mx, __shfl_xor_sync(~0u, mx, o));
    if (lane == 0) red[warp] = mx;
    __syncthreads();
    if (t == 0) { float m = red[0]; for (int w = 1; w < 8; w++) m = fmaxf(m, red[w]); red[8] = m; }
    __syncthreads();
    mx = red[8];

    float sum = 0.0f;
#pragma unroll
    for (int i = 0; i < 8; i++) {
        v[i].x = __expf(v[i].x - mx); v[i].y = __expf(v[i].y - mx);
        v[i].z = __expf(v[i].z - mx); v[i].w = __expf(v[i].w - mx);
        sum += (v[i].x + v[i].y) + (v[i].z + v[i].w);
    }
#pragma unroll
    for (int o = 16; o > 0; o >>= 1) sum += __shfl_xor_sync(~0u, sum, o);
    if (lane == 0) red[warp] = sum;
    __syncthreads();
    if (t == 0) { float s = 0.0f; for (int w = 0; w < 8; w++) s += red[w]; red[9] = s; }
    __syncthreads();
    const float inv = 1.0f / red[9];

#pragma unroll
    for (int i = 0; i < 8; i++) {
        float a = v[i].x * inv, b = v[i].y * inv, cc = v[i].z * inv, d = v[i].w * inv;
        __half h0 = __float2half(a), h1 = __float2half(b);
        __half h2 = __float2half(cc), h3 = __float2half(d);
        __half2 hA = __halves2half2(h0, h1), hB = __halves2half2(h2, h3);
        __half2 lA = __halves2half2(__float2half(a - __half2float(h0)), __float2half(b - __half2float(h1)));
        __half2 lB = __halves2half2(__float2half(cc - __half2float(h2)), __float2half(d - __half2float(h3)));
        const size_t idx = row * (N_TOK / 4) + (size_t)(i * 256 + t);
        ((uint2*)Ph)[idx] = make_uint2(*(uint32_t*)&hA, *(uint32_t*)&hB);
        ((uint2*)Pl)[idx] = make_uint2(*(uint32_t*)&lA, *(uint32_t*)&lB);
    }
}

// ----------------------------- launch --------------------------------------
extern "C" void kernel_launch(void* const* d_in, const int* in_sizes, int n_in,
                              void* d_out, int out_size)
{
    const float* emb = (const float*)d_in[0];
    const float* Wq  = (const float*)d_in[1];
    const float* bq  = (const float*)d_in[2];
    const float* Wk  = (const float*)d_in[3];
    const float* bk  = (const float*)d_in[4];
    const float* Wv  = (const float*)d_in[5];
    const float* bv  = (const float*)d_in[6];
    float* out = (float*)d_out;

    __half *eh, *el, *wh, *wl, *qh, *ql, *kh, *kl, *vth, *vtl, *ph, *pl;
    float* s;
    cudaGetSymbolAddress((void**)&eh, g_eh);   cudaGetSymbolAddress((void**)&el, g_el);
    cudaGetSymbolAddress((void**)&wh, g_wh);   cudaGetSymbolAddress((void**)&wl, g_wl);
    cudaGetSymbolAddress((void**)&qh, g_qh);   cudaGetSymbolAddress((void**)&ql, g_ql);
    cudaGetSymbolAddress((void**)&kh, g_kh);   cudaGetSymbolAddress((void**)&kl, g_kl);
    cudaGetSymbolAddress((void**)&vth, g_vth); cudaGetSymbolAddress((void**)&vtl, g_vtl);
    cudaGetSymbolAddress((void**)&s, g_s);
    cudaGetSymbolAddress((void**)&ph, g_ph);   cudaGetSymbolAddress((void**)&pl, g_pl);

    static int smem_set = 0;
    if (!smem_set) {
        cudaFuncSetAttribute(gemm_sp, cudaFuncAttributeMaxDynamicSharedMemorySize, GSMEM);
        smem_set = 1;
    }

    const size_t WSZ = (size_t)DIM * DIM;

    split_f32<<<(N_TOK * DIM / 4 + 255) / 256, 256>>>(emb, eh, el, N_TOK * DIM / 4);
    split_f32<<<(DIM * DIM / 4 + 255) / 256, 256>>>(Wq, wh, wl, DIM * DIM / 4);
    split_f32<<<(DIM * DIM / 4 + 255) / 256, 256>>>(Wk, wh + WSZ, wl + WSZ, DIM * DIM / 4);
    split_f32<<<(DIM * DIM / 4 + 255) / 256, 256>>>(Wv, wh + 2 * WSZ, wl + 2 * WSZ, DIM * DIM / 4);

    // Q = E @ Wq^T + bq  -> split [8192,1024]
    gemm_sp<<<dim3(8, 64), 256, GSMEM>>>(eh, el, DIM, wh, wl, DIM, bq, 1,
                                         nullptr, qh, ql, DIM, DIM, 1);
    // K = E @ Wk^T + bk  -> split
    gemm_sp<<<dim3(8, 64), 256, GSMEM>>>(eh, el, DIM, wh + WSZ, wl + WSZ, DIM, bk, 1,
                                         nullptr, kh, kl, DIM, DIM, 1);
    // V^T = Wv @ E^T + bv(per-row) -> split [1024,8192]
    gemm_sp<<<dim3(64, 8), 256, GSMEM>>>(wh + 2 * WSZ, wl + 2 * WSZ, DIM, eh, el, DIM, bv, 2,
                                         nullptr, vth, vtl, N_TOK, DIM, 1);
    // S = Q @ K^T  [8192,8192] fp32
    gemm_sp<<<dim3(64, 64), 256, GSMEM>>>(qh, ql, DIM, kh, kl, DIM, nullptr, 0,
                                          s, nullptr, nullptr, N_TOK, DIM, 0);
    // P = softmax(S) -> split
    softmax_split<<<N_TOK, 256>>>(s, ph, pl);
    // out = P @ (V^T)^T  [8192,1024] fp32
    gemm_sp<<<dim3(8, 64), 256, GSMEM>>>(ph, pl, N_TOK, vth, vtl, N_TOK, nullptr, 0,
                                         out, nullptr, nullptr, DIM, N_TOK, 0);
}

// round 5
// speedup vs baseline: 2.6445x; 1.2248x over previous
#include <cuda_runtime.h>
#include <cuda_fp16.h>
#include <cstdint>
#include <math.h>

#define N_TOK 8192
#define DIM   1024

// ----------------------------- scratch -------------------------------------
__device__ __align__(256) __half g_eh[(size_t)N_TOK * DIM];
__device__ __align__(256) __half g_el[(size_t)N_TOK * DIM];
__device__ __align__(256) __half g_wh[(size_t)3 * DIM * DIM];
__device__ __align__(256) __half g_wl[(size_t)3 * DIM * DIM];
__device__ __align__(256) __half g_qh[(size_t)N_TOK * DIM];
__device__ __align__(256) __half g_ql[(size_t)N_TOK * DIM];
__device__ __align__(256) __half g_kh[(size_t)N_TOK * DIM];
__device__ __align__(256) __half g_kl[(size_t)N_TOK * DIM];
__device__ __align__(256) __half g_vth[(size_t)DIM * N_TOK];  // V^T hi [D][N]
__device__ __align__(256) float  g_s[(size_t)N_TOK * N_TOK];
__device__ __align__(256) __half g_ph[(size_t)N_TOK * N_TOK];

// ----------------------------- helpers -------------------------------------
__device__ __forceinline__ uint32_t smem_u32(const void* p) {
    uint32_t a;
    asm("{ .reg .u64 t; cvta.to.shared.u64 t, %1; cvt.u32.u64 %0, t; }" : "=r"(a) : "l"(p));
    return a;
}
__device__ __forceinline__ void cp16(uint32_t dst, const void* src) {
    asm volatile("cp.async.cg.shared.global [%0], [%1], 16;" :: "r"(dst), "l"(src));
}
__device__ __forceinline__ void cp_commit() { asm volatile("cp.async.commit_group;" ::: "memory"); }
template <int N> __device__ __forceinline__ void cp_wait() {
    asm volatile("cp.async.wait_group %0;" :: "n"(N) : "memory");
}

#define LDSM4(r, addr) \
    asm volatile("ldmatrix.sync.aligned.m8n8.x4.shared.b16 {%0,%1,%2,%3}, [%4];" \
                 : "=r"((r)[0]), "=r"((r)[1]), "=r"((r)[2]), "=r"((r)[3]) : "r"(addr))

#define MMA16816(c, a, b0, b1) \
    asm volatile("mma.sync.aligned.m16n8k16.row.col.f32.f16.f16.f32 " \
                 "{%0,%1,%2,%3},{%4,%5,%6,%7},{%8,%9},{%0,%1,%2,%3};" \
                 : "+f"((c)[0]), "+f"((c)[1]), "+f"((c)[2]), "+f"((c)[3]) \
                 : "r"((a)[0]), "r"((a)[1]), "r"((a)[2]), "r"((a)[3]), "r"(b0), "r"(b1))

// ----------------------------- split GEMM ----------------------------------
// C[M,N] = A[M,K] @ B[N,K]^T (+bias), A/B given as fp16 hi(+lo) limb pairs.
// npass: 3 -> Ah*Bh + Al*Bh + Ah*Bl (fp32-grade), 1 -> Ah*Bh only.
// biasMode: 0 none, 1 per-col, 2 per-row.
// outMode: 0 -> f32 Cf, 1 -> Ch+Cl split, 2 -> Ch only.
// Tile 128x128, kc=32, 3-stage cp.async pipeline, 8 warps (2m x 4n).
#define KC 32
#define ROWP 80                 // smem row pitch (bytes): 64B data + 16B pad
#define TILEB (128 * ROWP)
#define STAGEB (4 * TILEB)      // Ah, Al, Bh, Bl slots (lo slots unused if npass==1)
#define GSMEM (3 * STAGEB)      // 122880 B

__global__ __launch_bounds__(256, 1)
void gemm_sp(const __half* __restrict__ Ah, const __half* __restrict__ Al, int lda,
             const __half* __restrict__ Bh, const __half* __restrict__ Bl, int ldb,
             const float* __restrict__ bias, int biasMode,
             float* __restrict__ Cf, __half* __restrict__ Ch, __half* __restrict__ Cl,
             int ldc, int K, int outMode, int npass)
{
    extern __shared__ char smem[];
    const uint32_t sb = smem_u32(smem);
    const int t = threadIdx.x, lane = t & 31, wid = t >> 5;
    const int wm = wid >> 2, wn = wid & 3;
    const int m0 = blockIdx.y * 128, n0 = blockIdx.x * 128;
    const int S = K / KC;
    const bool lo = (npass == 3);

    auto load_stage = [&](int s, int buf) {
        const int kt = s * KC;
        const uint32_t base = sb + (uint32_t)buf * STAGEB;
        // hi tiles always: Ah (tile 0), Bh (tile 2); lo tiles if 3-pass.
#pragma unroll
        for (int half = 0; half < 2; half++) {
            const int cid = half * 256 + t;        // 0..511
            const int row = cid >> 2, ch = cid & 3;
            const uint32_t off = row * ROWP + ch * 16;
            cp16(base + 0 * TILEB + off, Ah + (size_t)(m0 + row) * lda + kt + ch * 8);
            cp16(base + 2 * TILEB + off, Bh + (size_t)(n0 + row) * ldb + kt + ch * 8);
            if (lo) {
                cp16(base + 1 * TILEB + off, Al + (size_t)(m0 + row) * lda + kt + ch * 8);
                cp16(base + 3 * TILEB + off, Bl + (size_t)(n0 + row) * ldb + kt + ch * 8);
            }
        }
        cp_commit();
    };

    float c[4][4][4];
#pragma unroll
    for (int i = 0; i < 4; i++)
#pragma unroll
        for (int j = 0; j < 4; j++)
#pragma unroll
            for (int q = 0; q < 4; q++) c[i][j][q] = 0.0f;

    load_stage(0, 0);
    if (S > 1) load_stage(1, 1);
    if (S > 2) load_stage(2, 2);

    const uint32_t arow = (uint32_t)(wm * 64 + (lane & 15));
    const uint32_t brow = (uint32_t)(wn * 32 + (lane & 15));
    const uint32_t kbyte = ((lane >> 4) << 3) * 2;

    for (int s = 0; s < S; s++) {
        if (s < S - 2) cp_wait<2>(); else if (s == S - 2) cp_wait<1>(); else cp_wait<0>();
        __syncthreads();
        const uint32_t base = sb + (uint32_t)(s % 3) * STAGEB;

#pragma unroll
        for (int kh = 0; kh < 2; kh++) {
            const uint32_t ko = kh * 32 + kbyte;
            uint32_t ah[4][4], al[4][4], bh[2][4], bl[2][4];
#pragma unroll
            for (int mi = 0; mi < 4; mi++) {
                const uint32_t ro = (arow + mi * 16) * ROWP + ko;
                LDSM4(ah[mi], base + ro);
                if (lo) LDSM4(al[mi], base + TILEB + ro);
            }
#pragma unroll
            for (int g = 0; g < 2; g++) {
                const uint32_t ro = (brow + g * 16) * ROWP + ko;
                LDSM4(bh[g], base + 2 * TILEB + ro);
                if (lo) LDSM4(bl[g], base + 3 * TILEB + ro);
            }
#pragma unroll
            for (int mi = 0; mi < 4; mi++)
#pragma unroll
                for (int ni = 0; ni < 4; ni++)
                    MMA16816(c[mi][ni], ah[mi], bh[ni >> 1][ni & 1], bh[ni >> 1][(ni & 1) + 2]);
            if (lo) {
#pragma unroll
                for (int mi = 0; mi < 4; mi++)
#pragma unroll
                    for (int ni = 0; ni < 4; ni++)
                        MMA16816(c[mi][ni], al[mi], bh[ni >> 1][ni & 1], bh[ni >> 1][(ni & 1) + 2]);
#pragma unroll
                for (int mi = 0; mi < 4; mi++)
#pragma unroll
                    for (int ni = 0; ni < 4; ni++)
                        MMA16816(c[mi][ni], ah[mi], bl[ni >> 1][ni & 1], bl[ni >> 1][(ni & 1) + 2]);
            }
        }
        __syncthreads();
        if (s + 3 < S) load_stage(s + 3, s % 3);
    }

    // ----------------------------- epilogue --------------------------------
    const int rbase = m0 + wm * 64 + (lane >> 2);
    const int cbase = n0 + wn * 32 + (lane & 3) * 2;
#pragma unroll
    for (int mi = 0; mi < 4; mi++) {
#pragma unroll
        for (int ni = 0; ni < 4; ni++) {
            const int col = cbase + ni * 8;
            float bc0 = 0.0f, bc1 = 0.0f;
            if (biasMode == 1) { bc0 = bias[col]; bc1 = bias[col + 1]; }
#pragma unroll
            for (int h = 0; h < 2; h++) {
                const int row = rbase + mi * 16 + h * 8;
                float v0 = c[mi][ni][2 * h + 0] + bc0;
                float v1 = c[mi][ni][2 * h + 1] + bc1;
                if (biasMode == 2) { const float br = bias[row]; v0 += br; v1 += br; }
                const size_t off = (size_t)row * ldc + col;
                if (outMode == 0) {
                    *(float2*)(Cf + off) = make_float2(v0, v1);
                } else {
                    const __half h0 = __float2half(v0), h1 = __float2half(v1);
                    __half2 hp = __halves2half2(h0, h1);
                    *(uint32_t*)(Ch + off) = *(uint32_t*)&hp;
                    if (outMode == 1) {
                        const __half l0 = __float2half(v0 - __half2float(h0));
                        const __half l1 = __float2half(v1 - __half2float(h1));
                        __half2 lp = __halves2half2(l0, l1);
                        *(uint32_t*)(Cl + off) = *(uint32_t*)&lp;
                    }
                }
            }
        }
    }
}

// ----------------------------- elementwise split ---------------------------
__global__ __launch_bounds__(256)
void split_f32(const float* __restrict__ x, __half* __restrict__ h,
               __half* __restrict__ l, int n4)
{
    int i = blockIdx.x * 256 + threadIdx.x;
    if (i >= n4) return;
    float4 v = ((const float4*)x)[i];
    __half h0 = __float2half(v.x), h1 = __float2half(v.y);
    __half h2 = __float2half(v.z), h3 = __float2half(v.w);
    __half2 a = __halves2half2(h0, h1), b = __halves2half2(h2, h3);
    __half2 cc = __halves2half2(__float2half(v.x - __half2float(h0)), __float2half(v.y - __half2float(h1)));
    __half2 d = __halves2half2(__float2half(v.z - __half2float(h2)), __float2half(v.w - __half2float(h3)));
    ((uint2*)h)[i] = make_uint2(*(uint32_t*)&a, *(uint32_t*)&b);
    ((uint2*)l)[i] = make_uint2(*(uint32_t*)&cc, *(uint32_t*)&d);
}

// ----------------------------- softmax (hi-only fp16 out) ------------------
__global__ __launch_bounds__(256)
void softmax_hi(const float* __restrict__ S, __half* __restrict__ Ph)
{
    const size_t row = blockIdx.x;
    const float* p = S + row * N_TOK;
    const int t = threadIdx.x, lane = t & 31, warp = t >> 5;
    __shared__ float red[10];

    float4 v[8];
    float mx = -INFINITY;
#pragma unroll
    for (int i = 0; i < 8; i++) {
        v[i] = *(const float4*)(p + (size_t)(i * 256 + t) * 4);
        mx = fmaxf(mx, fmaxf(fmaxf(v[i].x, v[i].y), fmaxf(v[i].z, v[i].w)));
    }
#pragma unroll
    for (int o = 16; o > 0; o >>= 1) mx = fmaxf(mx, __shfl_xor_sync(~0u, mx, o));
    if (lane == 0) red[warp] = mx;
    __syncthreads();
    if (t == 0) { float m = red[0]; for (int w = 1; w < 8; w++) m = fmaxf(m, red[w]); red[8] = m; }
    __syncthreads();
    mx = red[8];

    float sum = 0.0f;
#pragma unroll
    for (int i = 0; i < 8; i++) {
        v[i].x = __expf(v[i].x - mx); v[i].y = __expf(v[i].y - mx);
        v[i].z = __expf(v[i].z - mx); v[i].w = __expf(v[i].w - mx);
        sum += (v[i].x + v[i].y) + (v[i].z + v[i].w);
    }
#pragma unroll
    for (int o = 16; o > 0; o >>= 1) sum += __shfl_xor_sync(~0u, sum, o);
    if (lane == 0) red[warp] = sum;
    __syncthreads();
    if (t == 0) { float s = 0.0f; for (int w = 0; w < 8; w++) s += red[w]; red[9] = s; }
    __syncthreads();
    const float inv = 1.0f / red[9];

#pragma unroll
    for (int i = 0; i < 8; i++) {
        __half2 hA = __halves2half2(__float2half(v[i].x * inv), __float2half(v[i].y * inv));
        __half2 hB = __halves2half2(__float2half(v[i].z * inv), __float2half(v[i].w * inv));
        const size_t idx = row * (N_TOK / 4) + (size_t)(i * 256 + t);
        ((uint2*)Ph)[idx] = make_uint2(*(uint32_t*)&hA, *(uint32_t*)&hB);
    }
}

// ----------------------------- launch --------------------------------------
extern "C" void kernel_launch(void* const* d_in, const int* in_sizes, int n_in,
                              void* d_out, int out_size)
{
    const float* emb = (const float*)d_in[0];
    const float* Wq  = (const float*)d_in[1];
    const float* bq  = (const float*)d_in[2];
    const float* Wk  = (const float*)d_in[3];
    const float* bk  = (const float*)d_in[4];
    const float* Wv  = (const float*)d_in[5];
    const float* bv  = (const float*)d_in[6];
    float* out = (float*)d_out;

    __half *eh, *el, *wh, *wl, *qh, *ql, *kh, *kl, *vth, *ph;
    float* s;
    cudaGetSymbolAddress((void**)&eh, g_eh);   cudaGetSymbolAddress((void**)&el, g_el);
    cudaGetSymbolAddress((void**)&wh, g_wh);   cudaGetSymbolAddress((void**)&wl, g_wl);
    cudaGetSymbolAddress((void**)&qh, g_qh);   cudaGetSymbolAddress((void**)&ql, g_ql);
    cudaGetSymbolAddress((void**)&kh, g_kh);   cudaGetSymbolAddress((void**)&kl, g_kl);
    cudaGetSymbolAddress((void**)&vth, g_vth);
    cudaGetSymbolAddress((void**)&s, g_s);
    cudaGetSymbolAddress((void**)&ph, g_ph);

    static int smem_set = 0;
    if (!smem_set) {
        cudaFuncSetAttribute(gemm_sp, cudaFuncAttributeMaxDynamicSharedMemorySize, GSMEM);
        smem_set = 1;
    }

    const size_t WSZ = (size_t)DIM * DIM;

    split_f32<<<(N_TOK * DIM / 4 + 255) / 256, 256>>>(emb, eh, el, N_TOK * DIM / 4);
    split_f32<<<(DIM * DIM / 4 + 255) / 256, 256>>>(Wq, wh, wl, DIM * DIM / 4);
    split_f32<<<(DIM * DIM / 4 + 255) / 256, 256>>>(Wk, wh + WSZ, wl + WSZ, DIM * DIM / 4);
    split_f32<<<(DIM * DIM / 4 + 255) / 256, 256>>>(Wv, wh + 2 * WSZ, wl + 2 * WSZ, DIM * DIM / 4);

    // Q = E @ Wq^T + bq  -> hi/lo split  (3-pass)
    gemm_sp<<<dim3(8, 64), 256, GSMEM>>>(eh, el, DIM, wh, wl, DIM, bq, 1,
                                         nullptr, qh, ql, DIM, DIM, 1, 3);
    // K = E @ Wk^T + bk  -> hi/lo split  (3-pass)
    gemm_sp<<<dim3(8, 64), 256, GSMEM>>>(eh, el, DIM, wh + WSZ, wl + WSZ, DIM, bk, 1,
                                         nullptr, kh, kl, DIM, DIM, 1, 3);
    // V^T = Wv @ E^T + bv(per-row) -> hi only  (3-pass)
    gemm_sp<<<dim3(64, 8), 256, GSMEM>>>(wh + 2 * WSZ, wl + 2 * WSZ, DIM, eh, el, DIM, bv, 2,
                                         nullptr, vth, nullptr, N_TOK, DIM, 2, 3);
    // S = Q @ K^T  [8192,8192] fp32  (3-pass; softmax sharpness demands it)
    gemm_sp<<<dim3(64, 64), 256, GSMEM>>>(qh, ql, DIM, kh, kl, DIM, nullptr, 0,
                                          s, nullptr, nullptr, N_TOK, DIM, 0, 3);
    // P = softmax(S) -> fp16 hi only
    softmax_hi<<<N_TOK, 256>>>(s, ph);
    // out = P @ (V^T)^T  [8192,1024] fp32  (1-pass: blend-insensitive stage)
    gemm_sp<<<dim3(8, 64), 256, GSMEM>>>(ph, nullptr, N_TOK, vth, nullptr, N_TOK, nullptr, 0,
                                         out, nullptr, nullptr, DIM, N_TOK, 0, 1);
}